// round 2
// baseline (speedup 1.0000x reference)
#include <cuda_runtime.h>
#include <math.h>

#define NN 100000
#define EE 800000
#define MNN 1000
#define MEE 8000
#define DD 128
#define HH 8
#define LL 16
#define BTT 256
#define VPP 15
#define SEE 10
#define RSQD 0.08838834764831845f

__device__ float g_feat[NN*DD];
__device__ float g_q[NN*DD];
__device__ float g_k[NN*DD];
__device__ float g_v[NN*DD];
__device__ float g_agg[NN*DD];
__device__ float g_mfeat[MNN*DD];
__device__ float g_mq[MNN*DD];
__device__ float g_mk[MNN*DD];
__device__ float g_mv[MNN*DD];
__device__ float g_magg[MNN*DD];
__device__ float g_mout[MNN*DD];
__device__ float g_mef[MEE*DD];
__device__ float g_p2mn[MNN*DD];
__device__ float g_p1mn[MNN*HH];
__device__ float g_p2me[MEE*DD];
__device__ float g_p1me[MEE*HH];
__device__ int g_deg[NN];
__device__ int g_rowptr[NN+1];
__device__ int g_cursor[NN];
__device__ int g_csr[EE];
__device__ int g_mdeg[MNN];
__device__ int g_mrowptr[MNN+1];
__device__ int g_mcursor[MNN];
__device__ int g_mcsr[MEE];

struct BaseP { float tw[HH]; float n1[HH]; float e1[HH]; float n2[DD]; float e2[DD]; };
__device__ BaseP g_base;

__global__ void k_zero_f(float* a, int n){
    int i = blockIdx.x*blockDim.x + threadIdx.x;
    if (i < n) a[i] = 0.0f;
}
__global__ void k_zero_i(int* a, int n){
    int i = blockIdx.x*blockDim.x + threadIdx.x;
    if (i < n) a[i] = 0;
}
__global__ void k_gather_rows(const float* __restrict__ emb, const int* __restrict__ vals,
                              float* __restrict__ out, int rows){
    int i = blockIdx.x*blockDim.x + threadIdx.x;
    if (i >= rows*32) return;
    int r = i >> 5, c = i & 31;
    ((float4*)out)[i] = ((const float4*)(emb + (size_t)vals[r]*DD))[c];
}
__global__ void k_hist(const int* __restrict__ dstv, int e, int* deg){
    int i = blockIdx.x*blockDim.x + threadIdx.x;
    if (i < e) atomicAdd(&deg[dstv[i]], 1);
}
__global__ void k_scan(const int* __restrict__ deg, int n, int* rowptr, int* cursor){
    __shared__ int part[1024];
    int tid = threadIdx.x;
    int chunk = (n + 1023) >> 10;
    int start = tid*chunk; if (start > n) start = n;
    int end = start + chunk; if (end > n) end = n;
    int s = 0;
    for (int i = start; i < end; i++) s += deg[i];
    part[tid] = s; __syncthreads();
    for (int off = 1; off < 1024; off <<= 1){
        int v = (tid >= off) ? part[tid-off] : 0;
        __syncthreads();
        part[tid] += v;
        __syncthreads();
    }
    int run = part[tid] - s;
    for (int i = start; i < end; i++){ rowptr[i] = run; cursor[i] = run; run += deg[i]; }
    if (end == n) rowptr[n] = run;
}
__global__ void k_scatter(const int* __restrict__ dstv, int e, int* cursor, int* csr){
    int i = blockIdx.x*blockDim.x + threadIdx.x;
    if (i < e){
        int p = atomicAdd(&cursor[dstv[i]], 1);
        csr[p] = i;
    }
}

__device__ __forceinline__ void warp_meta_learner(float4 xv, int lane,
        const float* __restrict__ u, const float* __restrict__ W2, const float* __restrict__ W1,
        float* p2_out, float* p1_out){
    float s[LL];
    #pragma unroll
    for (int l2 = 0; l2 < LL; l2++){
        float4 uv = *(const float4*)(u + l2*DD + lane*4);
        float p = xv.x*uv.x + xv.y*uv.y + xv.z*uv.z + xv.w*uv.w;
        p += __shfl_xor_sync(0xffffffffu, p, 1);
        p += __shfl_xor_sync(0xffffffffu, p, 2);
        p += __shfl_xor_sync(0xffffffffu, p, 4);
        p += __shfl_xor_sync(0xffffffffu, p, 8);
        p += __shfl_xor_sync(0xffffffffu, p, 16);
        s[l2] = p * RSQD;
    }
    float mx = s[0];
    #pragma unroll
    for (int i = 1; i < LL; i++) mx = fmaxf(mx, s[i]);
    float zz = 0.0f;
    #pragma unroll
    for (int i = 0; i < LL; i++){ s[i] = __expf(s[i]-mx); zz += s[i]; }
    float inv = 1.0f / zz;
    #pragma unroll
    for (int i = 0; i < LL; i++) s[i] *= inv;
    if (p2_out){
        float4 acc = make_float4(0,0,0,0);
        #pragma unroll
        for (int l2 = 0; l2 < LL; l2++){
            float4 wv = *(const float4*)(W2 + l2*DD + lane*4);
            acc.x += s[l2]*wv.x; acc.y += s[l2]*wv.y; acc.z += s[l2]*wv.z; acc.w += s[l2]*wv.w;
        }
        *(float4*)(p2_out + lane*4) = acc;
    }
    if (p1_out && lane < HH){
        float a = 0.0f;
        #pragma unroll
        for (int l2 = 0; l2 < LL; l2++) a += s[l2]*W1[l2*HH + lane];
        p1_out[lane] = a;
    }
}

__global__ void k_meta_learner(const float* __restrict__ X, int rows,
                               const float* __restrict__ u, const float* __restrict__ W2,
                               const float* __restrict__ W1,
                               float* __restrict__ p2, float* __restrict__ p1){
    int w = (blockIdx.x*blockDim.x + threadIdx.x) >> 5;
    int lane = threadIdx.x & 31;
    if (w >= rows) return;
    float4 xv = *(const float4*)(X + (size_t)w*DD + lane*4);
    warp_meta_learner(xv, lane, u, W2, W1, p2 + (size_t)w*DD, p1 + (size_t)w*HH);
}

__global__ void k_static(const float* __restrict__ emb, const int* __restrict__ svals,
                         const int* __restrict__ ssrc, const int* __restrict__ sdst,
                         const float* __restrict__ u, const float* __restrict__ W2,
                         const float* __restrict__ W1){
    __shared__ float sagg[VPP][DD];
    int lane = threadIdx.x;
    for (int r = 0; r < VPP; r++)
        for (int c = lane; c < DD; c += 32) sagg[r][c] = 0.0f;
    __syncwarp();
    for (int e = 0; e < SEE; e++){
        int rdst = sdst[e];
        const float* ev = emb + (size_t)svals[ssrc[e]]*DD;
        for (int c = lane; c < DD; c += 32) sagg[rdst][c] += ev[c];
    }
    __syncwarp();
    float4 x;
    x = *(float4*)&sagg[0][lane*4];  warp_meta_learner(x, lane, u, W2, W1, nullptr,   g_base.tw);
    x = *(float4*)&sagg[3][lane*4];  warp_meta_learner(x, lane, u, W2, W1, nullptr,   g_base.n1);
    x = *(float4*)&sagg[6][lane*4];  warp_meta_learner(x, lane, u, W2, W1, g_base.n2, nullptr);
    x = *(float4*)&sagg[9][lane*4];  warp_meta_learner(x, lane, u, W2, W1, nullptr,   g_base.e1);
    x = *(float4*)&sagg[12][lane*4]; warp_meta_learner(x, lane, u, W2, W1, g_base.e2, nullptr);
}

// GEMM qkv: O = A@W, row tile 64, all 128 cols. gridDim.y: 0=q,1=k,2=v.
__global__ __launch_bounds__(256) void k_gemm_qkv(
        const float* __restrict__ A, int rows,
        const float* __restrict__ Wq, const float* __restrict__ Wk, const float* __restrict__ Wv,
        float* __restrict__ Oq, float* __restrict__ Ok, float* __restrict__ Ov,
        const int* __restrict__ mid, const float* __restrict__ p2mn){
    __shared__ float As[64][64];
    __shared__ float Bs[64][128];
    int tid = threadIdx.x;
    int row0 = blockIdx.x*64;
    const float* W = (blockIdx.y == 0) ? Wq : (blockIdx.y == 1 ? Wk : Wv);
    float* O = (blockIdx.y == 0) ? Oq : (blockIdx.y == 1 ? Ok : Ov);
    int cx = tid & 31, cy = tid >> 5;
    float4 acc[8];
    #pragma unroll
    for (int j = 0; j < 8; j++) acc[j] = make_float4(0,0,0,0);
    for (int kp = 0; kp < 2; kp++){
        int ko = kp*64;
        #pragma unroll
        for (int i = 0; i < 4; i++){
            int f = i*256 + tid;
            int r = f >> 4, kc = f & 15;
            float4 av = make_float4(0,0,0,0);
            if (row0 + r < rows) av = *(const float4*)(A + (size_t)(row0+r)*DD + ko + kc*4);
            *(float4*)&As[r][kc*4] = av;
        }
        #pragma unroll
        for (int i = 0; i < 8; i++){
            int f = i*256 + tid;
            int r = f >> 5, c = f & 31;
            *(float4*)&Bs[r][c*4] = *(const float4*)(W + (size_t)(ko+r)*DD + c*4);
        }
        __syncthreads();
        #pragma unroll 8
        for (int kk = 0; kk < 64; kk++){
            float4 b = *(float4*)&Bs[kk][cx*4];
            #pragma unroll
            for (int j = 0; j < 8; j++){
                float a = As[cy*8 + j][kk];
                acc[j].x += a*b.x; acc[j].y += a*b.y; acc[j].z += a*b.z; acc[j].w += a*b.w;
            }
        }
        __syncthreads();
    }
    bool isq = (blockIdx.y == 0);
    #pragma unroll
    for (int j = 0; j < 8; j++){
        int r = row0 + cy*8 + j;
        if (r >= rows) continue;
        float4 o = acc[j];
        if (isq){
            float4 bn = *(float4*)&g_base.n2[cx*4];
            if (p2mn){
                float4 pm = *(const float4*)(p2mn + (size_t)mid[r]*DD + cx*4);
                bn.x += pm.x; bn.y += pm.y; bn.z += pm.z; bn.w += pm.w;
            }
            o.x *= bn.x; o.y *= bn.y; o.z *= bn.z; o.w *= bn.w;
        }
        *(float4*)(O + (size_t)r*DD + cx*4) = o;
    }
}

// O projection: v = relu(A@W); optional copy; feat_io += v (residual).
__global__ __launch_bounds__(256) void k_gemm_o(
        const float* __restrict__ A, int rows, const float* __restrict__ W,
        float* __restrict__ feat_io, float* __restrict__ out_copy){
    __shared__ float As[64][64];
    __shared__ float Bs[64][128];
    int tid = threadIdx.x;
    int row0 = blockIdx.x*64;
    int cx = tid & 31, cy = tid >> 5;
    float4 acc[8];
    #pragma unroll
    for (int j = 0; j < 8; j++) acc[j] = make_float4(0,0,0,0);
    for (int kp = 0; kp < 2; kp++){
        int ko = kp*64;
        #pragma unroll
        for (int i = 0; i < 4; i++){
            int f = i*256 + tid;
            int r = f >> 4, kc = f & 15;
            float4 av = make_float4(0,0,0,0);
            if (row0 + r < rows) av = *(const float4*)(A + (size_t)(row0+r)*DD + ko + kc*4);
            *(float4*)&As[r][kc*4] = av;
        }
        #pragma unroll
        for (int i = 0; i < 8; i++){
            int f = i*256 + tid;
            int r = f >> 5, c = f & 31;
            *(float4*)&Bs[r][c*4] = *(const float4*)(W + (size_t)(ko+r)*DD + c*4);
        }
        __syncthreads();
        #pragma unroll 8
        for (int kk = 0; kk < 64; kk++){
            float4 b = *(float4*)&Bs[kk][cx*4];
            #pragma unroll
            for (int j = 0; j < 8; j++){
                float a = As[cy*8 + j][kk];
                acc[j].x += a*b.x; acc[j].y += a*b.y; acc[j].z += a*b.z; acc[j].w += a*b.w;
            }
        }
        __syncthreads();
    }
    #pragma unroll
    for (int j = 0; j < 8; j++){
        int r = row0 + cy*8 + j;
        if (r >= rows) continue;
        size_t idx = (size_t)r*DD + cx*4;
        float4 v;
        v.x = fmaxf(acc[j].x, 0.0f); v.y = fmaxf(acc[j].y, 0.0f);
        v.z = fmaxf(acc[j].z, 0.0f); v.w = fmaxf(acc[j].w, 0.0f);
        if (out_copy) *(float4*)(out_copy + idx) = v;
        float4 f = *(float4*)(feat_io + idx);
        f.x += v.x; f.y += v.y; f.z += v.z; f.w += v.w;
        *(float4*)(feat_io + idx) = f;
    }
}

// warp per dst node, online softmax over incoming edges.
template<bool META>
__global__ void k_edge_conv(const int* __restrict__ rowptr, const int* __restrict__ csr,
                            const int* __restrict__ srcv, const int* __restrict__ meid_arr,
                            const int* __restrict__ mid_arr,
                            const float* __restrict__ q, const float* __restrict__ kf,
                            const float* __restrict__ vmat,
                            const float* __restrict__ p2me, const float* __restrict__ p1me,
                            const float* __restrict__ p1mn,
                            float* __restrict__ agg, float* __restrict__ keout, int n){
    int node = blockIdx.x*(blockDim.x >> 5) + (threadIdx.x >> 5);
    if (node >= n) return;
    int lane = threadIdx.x & 31, h = lane >> 2;
    float4 qv = *(const float4*)(q + (size_t)node*DD + lane*4);
    float p1n = g_base.n1[h];
    if (!META) p1n += p1mn[(size_t)mid_arr[node]*HH + h];
    float4 be2 = *(float4*)&g_base.e2[lane*4];
    float be1 = g_base.e1[h];
    float m = -INFINITY, z = 0.0f;
    float4 acc = make_float4(0,0,0,0);
    int i0 = rowptr[node], i1 = rowptr[node+1];
    for (int i = i0; i < i1; i++){
        int e = csr[i];
        int s = srcv[e];
        float4 kv = *(const float4*)(kf   + (size_t)s*DD + lane*4);
        float4 vv = *(const float4*)(vmat + (size_t)s*DD + lane*4);
        float4 p2 = be2; float e1 = be1;
        if (!META){
            int me = meid_arr[e];
            float4 pm = *(const float4*)(p2me + (size_t)me*DD + lane*4);
            p2.x += pm.x; p2.y += pm.y; p2.z += pm.z; p2.w += pm.w;
            e1 += p1me[(size_t)me*HH + h];
        }
        float4 ke;
        ke.x = kv.x*p2.x; ke.y = kv.y*p2.y; ke.z = kv.z*p2.z; ke.w = kv.w*p2.w;
        if (META) *(float4*)(keout + (size_t)e*DD + lane*4) = ke;
        float p = qv.x*ke.x + qv.y*ke.y + qv.z*ke.z + qv.w*ke.w;
        p += __shfl_xor_sync(0xffffffffu, p, 1);
        p += __shfl_xor_sync(0xffffffffu, p, 2);
        float score = p*0.25f + e1 + p1n;
        float mn = fmaxf(m, score);
        float c = __expf(m - mn);
        float w = __expf(score - mn);
        acc.x = acc.x*c + vv.x*w; acc.y = acc.y*c + vv.y*w;
        acc.z = acc.z*c + vv.z*w; acc.w = acc.w*c + vv.w*w;
        z = z*c + w; m = mn;
    }
    float inv = 1.0f / (z + 1e-9f);
    float4 o;
    o.x = acc.x*inv; o.y = acc.y*inv; o.z = acc.z*inv; o.w = acc.w*inv;
    *(float4*)(agg + (size_t)node*DD + lane*4) = o;
}

__global__ void k_readout(const float* __restrict__ feat, const int* __restrict__ tix,
                          const int* __restrict__ mid_arr, const float* __restrict__ p1mn,
                          float* __restrict__ out){
    int t = blockIdx.x*(blockDim.x >> 5) + (threadIdx.x >> 5);
    if (t >= BTT) return;
    int lane = threadIdx.x & 31, h = lane >> 2;
    int ti = tix[t];
    float4 f = *(const float4*)(feat + (size_t)ti*DD + lane*4);
    float s4 = f.x + f.y + f.z + f.w;
    float tw = g_base.tw[h] + p1mn[(size_t)mid_arr[ti]*HH + h];
    float p = tw * s4;
    p += __shfl_xor_sync(0xffffffffu, p, 1);
    p += __shfl_xor_sync(0xffffffffu, p, 2);
    p += __shfl_xor_sync(0xffffffffu, p, 4);
    p += __shfl_xor_sync(0xffffffffu, p, 8);
    p += __shfl_xor_sync(0xffffffffu, p, 16);
    if (lane == 0) out[t] += 0.5f * p;
}

extern "C" void kernel_launch(void* const* d_in, const int* in_sizes, int n_in,
                              void* d_out, int out_size){
    (void)in_sizes; (void)n_in; (void)out_size;
    const float* emb  = (const float*)d_in[0];
    const float* u    = (const float*)d_in[1];
    const float* W2l  = (const float*)d_in[2];
    const float* W1l  = (const float*)d_in[3];
    const float* Wq_m = (const float*)d_in[4];
    const float* Wk_m = (const float*)d_in[5];
    const float* Wv_m = (const float*)d_in[6];
    const float* Wo_m = (const float*)d_in[7];
    const float* Wq   = (const float*)d_in[8];
    const float* Wk   = (const float*)d_in[9];
    const float* Wv   = (const float*)d_in[10];
    const float* Wo   = (const float*)d_in[11];
    const int* node_vals      = (const int*)d_in[12];
    const int* meta_node_vals = (const int*)d_in[13];
    const int* srcv = (const int*)d_in[14];
    const int* dstv = (const int*)d_in[15];
    const int* msrc = (const int*)d_in[16];
    const int* mdst = (const int*)d_in[17];
    const int* mnid = (const int*)d_in[18];
    const int* meid = (const int*)d_in[19];
    const int* tix  = (const int*)d_in[20];
    const int* svals= (const int*)d_in[21];
    const int* ssrc = (const int*)d_in[22];
    const int* sdst = (const int*)d_in[23];
    float* out = (float*)d_out;

    void* vp;
    cudaGetSymbolAddress(&vp, g_feat);   float* p_feat  = (float*)vp;
    cudaGetSymbolAddress(&vp, g_q);      float* p_q     = (float*)vp;
    cudaGetSymbolAddress(&vp, g_k);      float* p_k     = (float*)vp;
    cudaGetSymbolAddress(&vp, g_v);      float* p_v     = (float*)vp;
    cudaGetSymbolAddress(&vp, g_agg);    float* p_agg   = (float*)vp;
    cudaGetSymbolAddress(&vp, g_mfeat);  float* p_mfeat = (float*)vp;
    cudaGetSymbolAddress(&vp, g_mq);     float* p_mq    = (float*)vp;
    cudaGetSymbolAddress(&vp, g_mk);     float* p_mk    = (float*)vp;
    cudaGetSymbolAddress(&vp, g_mv);     float* p_mv    = (float*)vp;
    cudaGetSymbolAddress(&vp, g_magg);   float* p_magg  = (float*)vp;
    cudaGetSymbolAddress(&vp, g_mout);   float* p_mout  = (float*)vp;
    cudaGetSymbolAddress(&vp, g_mef);    float* p_mef   = (float*)vp;
    cudaGetSymbolAddress(&vp, g_p2mn);   float* p_p2mn  = (float*)vp;
    cudaGetSymbolAddress(&vp, g_p1mn);   float* p_p1mn  = (float*)vp;
    cudaGetSymbolAddress(&vp, g_p2me);   float* p_p2me  = (float*)vp;
    cudaGetSymbolAddress(&vp, g_p1me);   float* p_p1me  = (float*)vp;
    cudaGetSymbolAddress(&vp, g_deg);     int* p_deg    = (int*)vp;
    cudaGetSymbolAddress(&vp, g_rowptr);  int* p_rowptr = (int*)vp;
    cudaGetSymbolAddress(&vp, g_cursor);  int* p_cursor = (int*)vp;
    cudaGetSymbolAddress(&vp, g_csr);     int* p_csr    = (int*)vp;
    cudaGetSymbolAddress(&vp, g_mdeg);    int* p_mdeg   = (int*)vp;
    cudaGetSymbolAddress(&vp, g_mrowptr); int* p_mrowptr= (int*)vp;
    cudaGetSymbolAddress(&vp, g_mcursor); int* p_mcursor= (int*)vp;
    cudaGetSymbolAddress(&vp, g_mcsr);    int* p_mcsr   = (int*)vp;

    // zero output
    k_zero_f<<<1, 256>>>(out, BTT);

    // CSR build: main graph
    k_zero_i<<<(NN+255)/256, 256>>>(p_deg, NN);
    k_hist<<<(EE+255)/256, 256>>>(dstv, EE, p_deg);
    k_scan<<<1, 1024>>>(p_deg, NN, p_rowptr, p_cursor);
    k_scatter<<<(EE+255)/256, 256>>>(dstv, EE, p_cursor, p_csr);
    // CSR build: meta graph
    k_zero_i<<<(MNN+255)/256, 256>>>(p_mdeg, MNN);
    k_hist<<<(MEE+255)/256, 256>>>(mdst, MEE, p_mdeg);
    k_scan<<<1, 1024>>>(p_mdeg, MNN, p_mrowptr, p_mcursor);
    k_scatter<<<(MEE+255)/256, 256>>>(mdst, MEE, p_mcursor, p_mcsr);

    // gather embeddings
    k_gather_rows<<<(NN*32+255)/256, 256>>>(emb, node_vals, p_feat, NN);
    k_gather_rows<<<(MNN*32+255)/256, 256>>>(emb, meta_node_vals, p_mfeat, MNN);

    // base params from static graph
    k_static<<<1, 32>>>(emb, svals, ssrc, sdst, u, W2l, W1l);

    const size_t WS = (size_t)DD*DD;
    for (int b = 0; b < 2; b++){
        // ---- meta conv ----
        dim3 gm((MNN+63)/64, 3);
        k_gemm_qkv<<<gm, 256>>>(p_mfeat, MNN, Wq_m + b*WS, Wk_m + b*WS, Wv_m + b*WS,
                                p_mq, p_mk, p_mv, nullptr, nullptr);
        k_edge_conv<true><<<(MNN+7)/8, 256>>>(p_mrowptr, p_mcsr, msrc, nullptr, nullptr,
                                              p_mq, p_mk, p_mv, nullptr, nullptr, nullptr,
                                              p_magg, p_mef, MNN);
        k_gemm_o<<<(MNN+63)/64, 256>>>(p_magg, MNN, Wo_m + b*WS, p_mfeat, p_mout);

        // ---- meta learner on conv outputs ----
        k_meta_learner<<<(MNN*32+255)/256, 256>>>(p_mout, MNN, u, W2l, W1l, p_p2mn, p_p1mn);
        k_meta_learner<<<(MEE*32+255)/256, 256>>>(p_mef, MEE, u, W2l, W1l, p_p2me, p_p1me);

        // ---- main conv ----
        dim3 gn((NN+63)/64, 3);
        k_gemm_qkv<<<gn, 256>>>(p_feat, NN, Wq + b*WS, Wk + b*WS, Wv + b*WS,
                                p_q, p_k, p_v, mnid, p_p2mn);
        k_edge_conv<false><<<(NN+7)/8, 256>>>(p_rowptr, p_csr, srcv, meid, mnid,
                                              p_q, p_k, p_v, p_p2me, p_p1me, p_p1mn,
                                              p_agg, nullptr, NN);
        k_gemm_o<<<(NN+63)/64, 256>>>(p_agg, NN, Wo + b*WS, p_feat, nullptr);

        // ---- readout ----
        k_readout<<<(BTT+7)/8, 256>>>(p_feat, tix, mnid, p_p1mn, out);
    }
}